// round 16
// baseline (speedup 1.0000x reference)
#include <cuda_runtime.h>
#include <cuda_fp16.h>
#include <cstdint>

#define NMAX 8192
#define D 256
#define MARGIN 0.2f
#define FULLW 0xFFFFFFFFu

// ---------------------------------------------------------------------------
// Scratch (allocation-free rule: __device__ globals)
// ---------------------------------------------------------------------------
__device__ float  g_diag[NMAX];
__device__ int    g_rank1[NMAX];
__device__ int    g_rank2[NMAX];
__device__ int    g_rowcost[NMAX];   // float bits, values >= 0
__device__ int    g_colcost[NMAX];   // float bits, values >= 0
__device__ unsigned int g_ctr;       // CTA arrival counter
__device__ __half g_Ah[NMAX * D];    // 4.2 MB
__device__ __half g_Bh[NMAX * D];    // 4.2 MB

// ---------------------------------------------------------------------------
// helpers
// ---------------------------------------------------------------------------
__device__ __forceinline__ uint32_t smem_u32(const void* p) {
    uint32_t a;
    asm("{ .reg .u64 t; cvta.to.shared.u64 t, %1; cvt.u32.u64 %0, t; }"
        : "=r"(a) : "l"(p));
    return a;
}
__device__ __forceinline__ void cp16(uint32_t dst, const void* src) {
    asm volatile("cp.async.cg.shared.global [%0], [%1], 16;"
                 :: "r"(dst), "l"(src));
}
__device__ __forceinline__ void mma_f16(float* d, const uint32_t* a, const uint32_t* b) {
    asm volatile(
        "mma.sync.aligned.m16n8k16.row.col.f32.f16.f16.f32 "
        "{%0,%1,%2,%3}, {%4,%5,%6,%7}, {%8,%9}, {%0,%1,%2,%3};"
        : "+f"(d[0]), "+f"(d[1]), "+f"(d[2]), "+f"(d[3])
        : "r"(a[0]), "r"(a[1]), "r"(a[2]), "r"(a[3]), "r"(b[0]), "r"(b[1]));
}
__device__ __forceinline__ uint32_t h2pack(float x, float y) {
    __half2 h = __floats2half2_rn(x, y);
    return *(uint32_t*)&h;
}
// Release-atomic arrival: orders our prior L2 atomics for any acquirer
// WITHOUT a gpu fence (no CCTL.IVALL / L1 flush — the R14 failure mode).
__device__ __forceinline__ unsigned int atom_add_release(unsigned int* p, unsigned int v) {
    unsigned int old;
    asm volatile("atom.release.gpu.global.add.u32 %0, [%1], %2;"
                 : "=r"(old) : "l"(p), "r"(v) : "memory");
    return old;
}
__device__ __forceinline__ unsigned int ld_acquire(const unsigned int* p) {
    unsigned int v;
    asm volatile("ld.acquire.gpu.global.u32 %0, [%1];" : "=r"(v) : "l"(p) : "memory");
    return v;
}

// ---------------------------------------------------------------------------
// prep: fused init + fp16 convert + diagonal. One warp per row.
// ---------------------------------------------------------------------------
__global__ void prep_kernel(const float* __restrict__ im,
                            const float* __restrict__ s,
                            float* out, int n) {
    int warp = (blockIdx.x * blockDim.x + threadIdx.x) >> 5;
    int lane = threadIdx.x & 31;
    if (warp >= n) return;

    size_t base = (size_t)warp * D + lane * 8;
    float4 a0 = *(const float4*)(im + base);
    float4 a1 = *(const float4*)(im + base + 4);
    float4 b0 = *(const float4*)(s + base);
    float4 b1 = *(const float4*)(s + base + 4);

    *(uint2*)(g_Ah + base)     = make_uint2(h2pack(a0.x, a0.y), h2pack(a0.z, a0.w));
    *(uint2*)(g_Ah + base + 4) = make_uint2(h2pack(a1.x, a1.y), h2pack(a1.z, a1.w));
    *(uint2*)(g_Bh + base)     = make_uint2(h2pack(b0.x, b0.y), h2pack(b0.z, b0.w));
    *(uint2*)(g_Bh + base + 4) = make_uint2(h2pack(b1.x, b1.y), h2pack(b1.z, b1.w));

    float acc = a0.x * b0.x + a0.y * b0.y + a0.z * b0.z + a0.w * b0.w
              + a1.x * b1.x + a1.y * b1.y + a1.z * b1.z + a1.w * b1.w;
#pragma unroll
    for (int o = 16; o > 0; o >>= 1) acc += __shfl_xor_sync(FULLW, acc, o);

    if (lane == 0) {
        g_diag[warp] = acc;
        g_rank1[warp] = 0; g_rank2[warp] = 0;
        g_rowcost[warp] = 0; g_colcost[warp] = 0;
        if (warp == 0) { out[0] = 0.0f; g_ctr = 0u; }
    }
}

// ---------------------------------------------------------------------------
// Fused mma.sync fp16 tile kernel: 128x128 score tile per CTA (R13 engine).
// 256 threads / 8 warps (4 M x 2 N), warp tile 32x64, m16n8k16,
// K=256, BK=64, double-buffered cp.async, one sync per stage, 2 CTAs/SM.
// Last CTA (release/acquire counter, NO threadfence) does the final reduce.
// ---------------------------------------------------------------------------
#define BM 128
#define BN 128
#define BK 64                    // halves per row per stage (128 B)
#define ROWPAD 36                // uint32 words per row (32 data + 4 pad)
#define NSTAGE (D / BK)          // 4
#define AS_WORDS (BM * ROWPAD)   // 4608 per stage
#define BS_WORDS (BN * ROWPAD)   // 4608 per stage
#define AS_OFF 0
#define BS_OFF (2 * AS_WORDS)                 // 9216
#define DIAGR_OFF (BS_OFF + 2 * BS_WORDS)     // 18432
#define DIAGC_OFF (DIAGR_OFF + 128)
#define RCNT_OFF  (DIAGC_OFF + 128)
#define RMAX_OFF  (RCNT_OFF + 128)
#define CCNT_OFF  (RMAX_OFF + 128)
#define CMAX_OFF  (CCNT_OFF + 128)
#define RED_OFF   (CMAX_OFF + 128)            // 8 floats cross-warp reduce
#define SMEM_WORDS (RED_OFF + 32)
#define SMEM_BYTES (SMEM_WORDS * 4)

__global__ __launch_bounds__(256, 2)
void tile_kernel(float* __restrict__ out, int nblocks) {
    extern __shared__ __align__(16) float smem[];
    uint32_t* smu = (uint32_t*)smem;
    int* sRCnt = (int*)(smem + RCNT_OFF);
    int* sRMax = (int*)(smem + RMAX_OFF);
    int* sCCnt = (int*)(smem + CCNT_OFF);
    int* sCMax = (int*)(smem + CMAX_OFF);

    const int tid  = threadIdx.x;
    const int wid  = tid >> 5;
    const int lane = tid & 31;
    const int wm   = wid >> 1;          // 0..3 -> M offset wm*32
    const int wn   = wid & 1;           // 0..1 -> N offset wn*64
    const int grp  = lane >> 2;         // 0..7
    const int tig  = lane & 3;          // 0..3
    const int i0 = blockIdx.y * BM;
    const int j0 = blockIdx.x * BN;
    const uint32_t sb = smem_u32(smem);

    if (tid < 128) {
        smem[DIAGR_OFF + tid] = g_diag[i0 + tid];
        smem[DIAGC_OFF + tid] = g_diag[j0 + tid];
        sRCnt[tid] = 0; sRMax[tid] = 0;
        sCCnt[tid] = 0; sCMax[tid] = 0;
    }

    float acc[2][8][4];
#pragma unroll
    for (int mt = 0; mt < 2; mt++)
#pragma unroll
        for (int nt = 0; nt < 8; nt++)
#pragma unroll
            for (int e = 0; e < 4; e++) acc[mt][nt][e] = 0.0f;

    const int ldrow = tid >> 3;         // 0..31 base row
    const int ldch  = tid & 7;          // chunk within row
    const __half* Abase = g_Ah + (size_t)(i0 + ldrow) * D + ldch * 8;
    const __half* Bbase = g_Bh + (size_t)(j0 + ldrow) * D + ldch * 8;

    // ---- prologue: stage 0 ----
    {
        uint32_t adst = sb + (AS_OFF + ldrow * ROWPAD + ldch * 4) * 4;
        uint32_t bdst = sb + (BS_OFF + ldrow * ROWPAD + ldch * 4) * 4;
#pragma unroll
        for (int q = 0; q < 4; q++)
            cp16(adst + q * 32 * ROWPAD * 4, Abase + (size_t)(q * 32) * D);
#pragma unroll
        for (int q = 0; q < 4; q++)
            cp16(bdst + q * 32 * ROWPAD * 4, Bbase + (size_t)(q * 32) * D);
        asm volatile("cp.async.commit_group;");
    }

#pragma unroll
    for (int st = 0; st < NSTAGE; st++) {
        const int cur = st & 1;
        asm volatile("cp.async.wait_group 0;");
        __syncthreads();    // stage st data visible + prior compute retired

        if (st + 1 < NSTAGE) {
            const int nxt = (st + 1) & 1;
            uint32_t adst = sb + (AS_OFF + nxt * AS_WORDS + ldrow * ROWPAD + ldch * 4) * 4;
            uint32_t bdst = sb + (BS_OFF + nxt * BS_WORDS + ldrow * ROWPAD + ldch * 4) * 4;
            const __half* as = Abase + (st + 1) * BK;
            const __half* bs = Bbase + (st + 1) * BK;
#pragma unroll
            for (int q = 0; q < 4; q++)
                cp16(adst + q * 32 * ROWPAD * 4, as + (size_t)(q * 32) * D);
#pragma unroll
            for (int q = 0; q < 4; q++)
                cp16(bdst + q * 32 * ROWPAD * 4, bs + (size_t)(q * 32) * D);
            asm volatile("cp.async.commit_group;");
        }

        const uint32_t* As = smu + AS_OFF + cur * AS_WORDS;
        const uint32_t* Bs = smu + BS_OFF + cur * BS_WORDS;
#pragma unroll
        for (int k16 = 0; k16 < BK / 16; k16++) {
            uint32_t fa[2][4], fb[8][2];
#pragma unroll
            for (int mt = 0; mt < 2; mt++) {
                const uint32_t* ap = As + (wm * 32 + mt * 16 + grp) * ROWPAD + k16 * 8 + tig;
                fa[mt][0] = ap[0];
                fa[mt][1] = ap[8 * ROWPAD];
                fa[mt][2] = ap[4];
                fa[mt][3] = ap[8 * ROWPAD + 4];
            }
#pragma unroll
            for (int nt = 0; nt < 8; nt++) {
                const uint32_t* bp = Bs + (wn * 64 + nt * 8 + grp) * ROWPAD + k16 * 8 + tig;
                fb[nt][0] = bp[0];
                fb[nt][1] = bp[4];
            }
#pragma unroll
            for (int nt = 0; nt < 8; nt++)
#pragma unroll
                for (int mt = 0; mt < 2; mt++)
                    mma_f16(acc[mt][nt], fa[mt], fb[nt]);
        }
    }
    __syncthreads();   // retire last stage's compute before epilogue

    // ---- epilogue: row stats ----
#pragma unroll
    for (int mt = 0; mt < 2; mt++) {
#pragma unroll
        for (int h = 0; h < 2; h++) {
            const int rin = wm * 32 + mt * 16 + grp + h * 8;
            const int gi = i0 + rin;
            const float dr = smem[DIAGR_OFF + rin];
            int cnt = 0;
            float rmax = 0.0f;
#pragma unroll
            for (int nt = 0; nt < 8; nt++) {
#pragma unroll
                for (int e = 0; e < 2; e++) {
                    const int cin = wn * 64 + nt * 8 + 2 * tig + e;
                    float v = acc[mt][nt][h * 2 + e];
                    bool od = (gi != j0 + cin);
                    cnt += (od && (v < dr));
                    if (od) rmax = fmaxf(rmax, (MARGIN + v) - dr);
                }
            }
            cnt  += __shfl_xor_sync(FULLW, cnt, 1);
            rmax  = fmaxf(rmax, __shfl_xor_sync(FULLW, rmax, 1));
            cnt  += __shfl_xor_sync(FULLW, cnt, 2);
            rmax  = fmaxf(rmax, __shfl_xor_sync(FULLW, rmax, 2));
            if (tig == 0) {
                atomicAdd(&sRCnt[rin], cnt);
                atomicMax(&sRMax[rin], __float_as_int(rmax));
            }
        }
    }
    // ---- epilogue: col stats ----
#pragma unroll
    for (int nt = 0; nt < 8; nt++) {
#pragma unroll
        for (int e = 0; e < 2; e++) {
            const int cin = wn * 64 + nt * 8 + 2 * tig + e;
            const float dc = smem[DIAGC_OFF + cin];
            int cnt = 0;
            float cmax = 0.0f;
#pragma unroll
            for (int mt = 0; mt < 2; mt++) {
#pragma unroll
                for (int h = 0; h < 2; h++) {
                    const int gi = i0 + wm * 32 + mt * 16 + grp + h * 8;
                    float v = acc[mt][nt][h * 2 + e];
                    bool od = (gi != j0 + cin);
                    cnt += (od && (v < dc));
                    if (od) cmax = fmaxf(cmax, (MARGIN + v) - dc);
                }
            }
            cnt  += __shfl_xor_sync(FULLW, cnt, 4);
            cmax  = fmaxf(cmax, __shfl_xor_sync(FULLW, cmax, 4));
            cnt  += __shfl_xor_sync(FULLW, cnt, 8);
            cmax  = fmaxf(cmax, __shfl_xor_sync(FULLW, cmax, 8));
            cnt  += __shfl_xor_sync(FULLW, cnt, 16);
            cmax  = fmaxf(cmax, __shfl_xor_sync(FULLW, cmax, 16));
            if (grp == 0) {
                atomicAdd(&sCCnt[cin], cnt);
                atomicMax(&sCMax[cin], __float_as_int(cmax));
            }
        }
    }
    __syncthreads();

    if (tid < 128) {
        atomicAdd(&g_rank1[i0 + tid], sRCnt[tid]);
        atomicMax(&g_rowcost[i0 + tid], sRMax[tid]);
        atomicAdd(&g_rank2[j0 + tid], sCCnt[tid]);
        atomicMax(&g_colcost[j0 + tid], sCMax[tid]);
    }
    __syncthreads();   // all 4 global atomics issued before arrival

    // ---- last-CTA final reduction (release/acquire, no threadfence) ----
    __shared__ int sIsLast;
    if (tid == 0) {
        // release orders our L2 atomics above for any acquiring observer
        unsigned int c = atom_add_release(&g_ctr, 1u);
        sIsLast = (c == (unsigned int)(nblocks - 1));
    }
    __syncthreads();
    if (!sIsLast) return;

    if (tid == 0) (void)ld_acquire(&g_ctr);   // acquire: peers' releases visible
    __syncthreads();

    // Deterministic fixed-order reduction; __ldcg reads straight from L2.
    float sum = 0.0f;
#pragma unroll
    for (int v = 0; v < 8; v++) {
        int i = tid + v * 256;                  // 2048 int4 groups
        int4 r1 = __ldcg((const int4*)g_rank1 + i);
        int4 r2 = __ldcg((const int4*)g_rank2 + i);
        int4 rc = __ldcg((const int4*)g_rowcost + i);
        int4 cc = __ldcg((const int4*)g_colcost + i);
        sum += __int_as_float(rc.x) / ((float)r1.x + 1.0f)
             + __int_as_float(rc.y) / ((float)r1.y + 1.0f)
             + __int_as_float(rc.z) / ((float)r1.z + 1.0f)
             + __int_as_float(rc.w) / ((float)r1.w + 1.0f)
             + __int_as_float(cc.x) / ((float)r2.x + 1.0f)
             + __int_as_float(cc.y) / ((float)r2.y + 1.0f)
             + __int_as_float(cc.z) / ((float)r2.z + 1.0f)
             + __int_as_float(cc.w) / ((float)r2.w + 1.0f);
    }
#pragma unroll
    for (int o = 16; o > 0; o >>= 1) sum += __shfl_xor_sync(FULLW, sum, o);
    if (lane == 0) smem[RED_OFF + wid] = sum;
    __syncthreads();
    if (tid == 0) {
        float t = 0.0f;
#pragma unroll
        for (int w = 0; w < 8; w++) t += smem[RED_OFF + w];
        out[0] = t;
    }
}

// ---------------------------------------------------------------------------
extern "C" void kernel_launch(void* const* d_in, const int* in_sizes, int n_in,
                              void* d_out, int out_size) {
    const float* im = (const float*)d_in[0];
    const float* s  = (const float*)d_in[1];
    float* out = (float*)d_out;
    const int n = in_sizes[0] / D;   // 8192

    cudaFuncSetAttribute(tile_kernel,
                         cudaFuncAttributeMaxDynamicSharedMemorySize, SMEM_BYTES);

    prep_kernel<<<(n * 32 + 255) / 256, 256>>>(im, s, out, n);
    dim3 grid(n / BN, n / BM);
    tile_kernel<<<grid, 256, SMEM_BYTES>>>(out, grid.x * grid.y);
}

// round 17
// speedup vs baseline: 1.1237x; 1.1237x over previous
#include <cuda_runtime.h>
#include <cuda_fp16.h>
#include <cstdint>

#define NMAX 8192
#define D 256
#define MARGIN 0.2f
#define FULLW 0xFFFFFFFFu

// ---------------------------------------------------------------------------
// Scratch (allocation-free rule: __device__ globals)
// ---------------------------------------------------------------------------
__device__ float  g_diag[NMAX];
__device__ int    g_rank1[NMAX];
__device__ int    g_rank2[NMAX];
__device__ int    g_rowcost[NMAX];   // float bits, values >= 0
__device__ int    g_colcost[NMAX];   // float bits, values >= 0
__device__ __half g_Ah[NMAX * D];    // 4.2 MB
__device__ __half g_Bh[NMAX * D];    // 4.2 MB

// ---------------------------------------------------------------------------
// helpers
// ---------------------------------------------------------------------------
__device__ __forceinline__ uint32_t smem_u32(const void* p) {
    uint32_t a;
    asm("{ .reg .u64 t; cvta.to.shared.u64 t, %1; cvt.u32.u64 %0, t; }"
        : "=r"(a) : "l"(p));
    return a;
}
__device__ __forceinline__ void cp16(uint32_t dst, const void* src) {
    asm volatile("cp.async.cg.shared.global [%0], [%1], 16;"
                 :: "r"(dst), "l"(src));
}
__device__ __forceinline__ void mma_f16(float* d, const uint32_t* a, const uint32_t* b) {
    asm volatile(
        "mma.sync.aligned.m16n8k16.row.col.f32.f16.f16.f32 "
        "{%0,%1,%2,%3}, {%4,%5,%6,%7}, {%8,%9}, {%0,%1,%2,%3};"
        : "+f"(d[0]), "+f"(d[1]), "+f"(d[2]), "+f"(d[3])
        : "r"(a[0]), "r"(a[1]), "r"(a[2]), "r"(a[3]), "r"(b[0]), "r"(b[1]));
}
__device__ __forceinline__ void ldsm_x4(uint32_t& r0, uint32_t& r1,
                                        uint32_t& r2, uint32_t& r3, uint32_t addr) {
    asm volatile("ldmatrix.sync.aligned.m8n8.x4.shared.b16 {%0,%1,%2,%3}, [%4];"
                 : "=r"(r0), "=r"(r1), "=r"(r2), "=r"(r3) : "r"(addr));
}
__device__ __forceinline__ uint32_t h2pack(float x, float y) {
    __half2 h = __floats2half2_rn(x, y);
    return *(uint32_t*)&h;
}

// ---------------------------------------------------------------------------
// prep: fused init + fp16 convert + diagonal. One warp per row.
// ---------------------------------------------------------------------------
__global__ void prep_kernel(const float* __restrict__ im,
                            const float* __restrict__ s,
                            float* out, int n) {
    int warp = (blockIdx.x * blockDim.x + threadIdx.x) >> 5;
    int lane = threadIdx.x & 31;
    if (warp >= n) return;

    size_t base = (size_t)warp * D + lane * 8;
    float4 a0 = *(const float4*)(im + base);
    float4 a1 = *(const float4*)(im + base + 4);
    float4 b0 = *(const float4*)(s + base);
    float4 b1 = *(const float4*)(s + base + 4);

    *(uint2*)(g_Ah + base)     = make_uint2(h2pack(a0.x, a0.y), h2pack(a0.z, a0.w));
    *(uint2*)(g_Ah + base + 4) = make_uint2(h2pack(a1.x, a1.y), h2pack(a1.z, a1.w));
    *(uint2*)(g_Bh + base)     = make_uint2(h2pack(b0.x, b0.y), h2pack(b0.z, b0.w));
    *(uint2*)(g_Bh + base + 4) = make_uint2(h2pack(b1.x, b1.y), h2pack(b1.z, b1.w));

    float acc = a0.x * b0.x + a0.y * b0.y + a0.z * b0.z + a0.w * b0.w
              + a1.x * b1.x + a1.y * b1.y + a1.z * b1.z + a1.w * b1.w;
#pragma unroll
    for (int o = 16; o > 0; o >>= 1) acc += __shfl_xor_sync(FULLW, acc, o);

    if (lane == 0) {
        g_diag[warp] = acc;
        g_rank1[warp] = 0; g_rank2[warp] = 0;
        g_rowcost[warp] = 0; g_colcost[warp] = 0;
        if (warp == 0) out[0] = 0.0f;
    }
}

// ---------------------------------------------------------------------------
// Fused mma.sync fp16 tile kernel: 128x128 score tile per CTA (R13 engine,
// fragments loaded via ldmatrix.x4 instead of 24 scalar LDS per k16).
// 256 threads / 8 warps (4 M x 2 N), warp tile 32x64, m16n8k16,
// K=256, BK=64, double-buffered cp.async, one sync per stage, 2 CTAs/SM.
// ---------------------------------------------------------------------------
#define BM 128
#define BN 128
#define BK 64                    // halves per row per stage (128 B)
#define ROWPAD 36                // uint32 words per row (32 data + 4 pad)
#define NSTAGE (D / BK)          // 4
#define AS_WORDS (BM * ROWPAD)   // 4608 per stage
#define BS_WORDS (BN * ROWPAD)   // 4608 per stage
#define AS_OFF 0
#define BS_OFF (2 * AS_WORDS)                 // 9216
#define DIAGR_OFF (BS_OFF + 2 * BS_WORDS)     // 18432
#define DIAGC_OFF (DIAGR_OFF + 128)
#define RCNT_OFF  (DIAGC_OFF + 128)
#define RMAX_OFF  (RCNT_OFF + 128)
#define CCNT_OFF  (RMAX_OFF + 128)
#define CMAX_OFF  (CCNT_OFF + 128)
#define SMEM_WORDS (CMAX_OFF + 128)           // 19200
#define SMEM_BYTES (SMEM_WORDS * 4)           // 76800

__global__ __launch_bounds__(256, 2)
void tile_kernel() {
    extern __shared__ __align__(16) float smem[];
    int* sRCnt = (int*)(smem + RCNT_OFF);
    int* sRMax = (int*)(smem + RMAX_OFF);
    int* sCCnt = (int*)(smem + CCNT_OFF);
    int* sCMax = (int*)(smem + CMAX_OFF);

    const int tid  = threadIdx.x;
    const int wid  = tid >> 5;
    const int lane = tid & 31;
    const int wm   = wid >> 1;          // 0..3 -> M offset wm*32
    const int wn   = wid & 1;           // 0..1 -> N offset wn*64
    const int grp  = lane >> 2;         // 0..7
    const int tig  = lane & 3;          // 0..3
    const int i0 = blockIdx.y * BM;
    const int j0 = blockIdx.x * BN;
    const uint32_t sb = smem_u32(smem);

    if (tid < 128) {
        smem[DIAGR_OFF + tid] = g_diag[i0 + tid];
        smem[DIAGC_OFF + tid] = g_diag[j0 + tid];
        sRCnt[tid] = 0; sRMax[tid] = 0;
        sCCnt[tid] = 0; sCMax[tid] = 0;
    }

    float acc[2][8][4];
#pragma unroll
    for (int mt = 0; mt < 2; mt++)
#pragma unroll
        for (int nt = 0; nt < 8; nt++)
#pragma unroll
            for (int e = 0; e < 4; e++) acc[mt][nt][e] = 0.0f;

    const int ldrow = tid >> 3;         // 0..31 base row
    const int ldch  = tid & 7;          // chunk within row
    const __half* Abase = g_Ah + (size_t)(i0 + ldrow) * D + ldch * 8;
    const __half* Bbase = g_Bh + (size_t)(j0 + ldrow) * D + ldch * 8;

    // ldmatrix per-lane addresses (word offsets within a stage buffer):
    // A tile mt: matrices [r0-7,k0-7],[r8-15,k0-7],[r0-7,k8-15],[r8-15,k8-15]
    //   lane row = wm*32 + mt*16 + (lane&15); k-ext word = (lane>>4)*4
    // B x4 #q covers nt=2q,2q+1 (matrices: nt0/k0-7, nt0/k8-15, nt1/k0-7, nt1/k8-15)
    //   lane row = wn*64 + q*16 + ((lane>>4)<<3) + (lane&7); k-ext = ((lane>>3)&1)*4
    const uint32_t a_lane_word = (uint32_t)((wm * 32 + (lane & 15)) * ROWPAD + (lane >> 4) * 4);
    const uint32_t b_lane_word = (uint32_t)((wn * 64 + ((lane >> 4) << 3) + (lane & 7)) * ROWPAD
                                            + ((lane >> 3) & 1) * 4);

    // ---- prologue: stage 0 ----
    {
        uint32_t adst = sb + (AS_OFF + ldrow * ROWPAD + ldch * 4) * 4;
        uint32_t bdst = sb + (BS_OFF + ldrow * ROWPAD + ldch * 4) * 4;
#pragma unroll
        for (int q = 0; q < 4; q++)
            cp16(adst + q * 32 * ROWPAD * 4, Abase + (size_t)(q * 32) * D);
#pragma unroll
        for (int q = 0; q < 4; q++)
            cp16(bdst + q * 32 * ROWPAD * 4, Bbase + (size_t)(q * 32) * D);
        asm volatile("cp.async.commit_group;");
    }

#pragma unroll
    for (int st = 0; st < NSTAGE; st++) {
        const int cur = st & 1;
        asm volatile("cp.async.wait_group 0;");
        __syncthreads();    // stage st data visible + prior compute retired

        if (st + 1 < NSTAGE) {
            const int nxt = (st + 1) & 1;
            uint32_t adst = sb + (AS_OFF + nxt * AS_WORDS + ldrow * ROWPAD + ldch * 4) * 4;
            uint32_t bdst = sb + (BS_OFF + nxt * BS_WORDS + ldrow * ROWPAD + ldch * 4) * 4;
            const __half* as = Abase + (st + 1) * BK;
            const __half* bs = Bbase + (st + 1) * BK;
#pragma unroll
            for (int q = 0; q < 4; q++)
                cp16(adst + q * 32 * ROWPAD * 4, as + (size_t)(q * 32) * D);
#pragma unroll
            for (int q = 0; q < 4; q++)
                cp16(bdst + q * 32 * ROWPAD * 4, bs + (size_t)(q * 32) * D);
            asm volatile("cp.async.commit_group;");
        }

        const uint32_t a_stage = sb + (AS_OFF + cur * AS_WORDS + a_lane_word) * 4;
        const uint32_t b_stage = sb + (BS_OFF + cur * BS_WORDS + b_lane_word) * 4;
#pragma unroll
        for (int k16 = 0; k16 < BK / 16; k16++) {
            uint32_t fa[2][4], fb[8][2];
#pragma unroll
            for (int mt = 0; mt < 2; mt++)
                ldsm_x4(fa[mt][0], fa[mt][1], fa[mt][2], fa[mt][3],
                        a_stage + (mt * 16 * ROWPAD + k16 * 8) * 4);
#pragma unroll
            for (int q = 0; q < 4; q++)
                ldsm_x4(fb[2 * q][0], fb[2 * q][1], fb[2 * q + 1][0], fb[2 * q + 1][1],
                        b_stage + (q * 16 * ROWPAD + k16 * 8) * 4);
#pragma unroll
            for (int nt = 0; nt < 8; nt++)
#pragma unroll
                for (int mt = 0; mt < 2; mt++)
                    mma_f16(acc[mt][nt], fa[mt], fb[nt]);
        }
    }
    __syncthreads();   // retire last stage's compute before epilogue

    // ---- epilogue: row stats ----
#pragma unroll
    for (int mt = 0; mt < 2; mt++) {
#pragma unroll
        for (int h = 0; h < 2; h++) {
            const int rin = wm * 32 + mt * 16 + grp + h * 8;
            const int gi = i0 + rin;
            const float dr = smem[DIAGR_OFF + rin];
            int cnt = 0;
            float rmax = 0.0f;
#pragma unroll
            for (int nt = 0; nt < 8; nt++) {
#pragma unroll
                for (int e = 0; e < 2; e++) {
                    const int cin = wn * 64 + nt * 8 + 2 * tig + e;
                    float v = acc[mt][nt][h * 2 + e];
                    bool od = (gi != j0 + cin);
                    cnt += (od && (v < dr));
                    if (od) rmax = fmaxf(rmax, (MARGIN + v) - dr);
                }
            }
            cnt  += __shfl_xor_sync(FULLW, cnt, 1);
            rmax  = fmaxf(rmax, __shfl_xor_sync(FULLW, rmax, 1));
            cnt  += __shfl_xor_sync(FULLW, cnt, 2);
            rmax  = fmaxf(rmax, __shfl_xor_sync(FULLW, rmax, 2));
            if (tig == 0) {
                atomicAdd(&sRCnt[rin], cnt);
                atomicMax(&sRMax[rin], __float_as_int(rmax));
            }
        }
    }
    // ---- epilogue: col stats ----
#pragma unroll
    for (int nt = 0; nt < 8; nt++) {
#pragma unroll
        for (int e = 0; e < 2; e++) {
            const int cin = wn * 64 + nt * 8 + 2 * tig + e;
            const float dc = smem[DIAGC_OFF + cin];
            int cnt = 0;
            float cmax = 0.0f;
#pragma unroll
            for (int mt = 0; mt < 2; mt++) {
#pragma unroll
                for (int h = 0; h < 2; h++) {
                    const int gi = i0 + wm * 32 + mt * 16 + grp + h * 8;
                    float v = acc[mt][nt][h * 2 + e];
                    bool od = (gi != j0 + cin);
                    cnt += (od && (v < dc));
                    if (od) cmax = fmaxf(cmax, (MARGIN + v) - dc);
                }
            }
            cnt  += __shfl_xor_sync(FULLW, cnt, 4);
            cmax  = fmaxf(cmax, __shfl_xor_sync(FULLW, cmax, 4));
            cnt  += __shfl_xor_sync(FULLW, cnt, 8);
            cmax  = fmaxf(cmax, __shfl_xor_sync(FULLW, cmax, 8));
            cnt  += __shfl_xor_sync(FULLW, cnt, 16);
            cmax  = fmaxf(cmax, __shfl_xor_sync(FULLW, cmax, 16));
            if (grp == 0) {
                atomicAdd(&sCCnt[cin], cnt);
                atomicMax(&sCMax[cin], __float_as_int(cmax));
            }
        }
    }
    __syncthreads();

    if (tid < 128) {
        atomicAdd(&g_rank1[i0 + tid], sRCnt[tid]);
        atomicMax(&g_rowcost[i0 + tid], sRMax[tid]);
        atomicAdd(&g_rank2[j0 + tid], sCCnt[tid]);
        atomicMax(&g_colcost[j0 + tid], sCMax[tid]);
    }
}

// ---------------------------------------------------------------------------
// Deterministic final reduction
// ---------------------------------------------------------------------------
__global__ void final_kernel(float* out, int n) {
    __shared__ float red[32];
    const int t = threadIdx.x;
    const int nv = n / 4;
    float sum = 0.0f;
#pragma unroll
    for (int v = 0; v < 2; v++) {
        int i = t + v * 1024;
        if (i < nv) {
            int4 r1 = ((const int4*)g_rank1)[i];
            int4 r2 = ((const int4*)g_rank2)[i];
            int4 rc = ((const int4*)g_rowcost)[i];
            int4 cc = ((const int4*)g_colcost)[i];
            sum += __int_as_float(rc.x) / ((float)r1.x + 1.0f)
                 + __int_as_float(rc.y) / ((float)r1.y + 1.0f)
                 + __int_as_float(rc.z) / ((float)r1.z + 1.0f)
                 + __int_as_float(rc.w) / ((float)r1.w + 1.0f)
                 + __int_as_float(cc.x) / ((float)r2.x + 1.0f)
                 + __int_as_float(cc.y) / ((float)r2.y + 1.0f)
                 + __int_as_float(cc.z) / ((float)r2.z + 1.0f)
                 + __int_as_float(cc.w) / ((float)r2.w + 1.0f);
        }
    }
#pragma unroll
    for (int o = 16; o > 0; o >>= 1) sum += __shfl_xor_sync(FULLW, sum, o);
    if ((t & 31) == 0) red[t >> 5] = sum;
    __syncthreads();
    if (t < 32) {
        float v = red[t];
#pragma unroll
        for (int o = 16; o > 0; o >>= 1) v += __shfl_xor_sync(FULLW, v, o);
        if (t == 0) out[0] = v;
    }
}

// ---------------------------------------------------------------------------
extern "C" void kernel_launch(void* const* d_in, const int* in_sizes, int n_in,
                              void* d_out, int out_size) {
    const float* im = (const float*)d_in[0];
    const float* s  = (const float*)d_in[1];
    float* out = (float*)d_out;
    const int n = in_sizes[0] / D;   // 8192

    cudaFuncSetAttribute(tile_kernel,
                         cudaFuncAttributeMaxDynamicSharedMemorySize, SMEM_BYTES);

    prep_kernel<<<(n * 32 + 255) / 256, 256>>>(im, s, out, n);
    dim3 grid(n / BN, n / BM);
    tile_kernel<<<grid, 256, SMEM_BYTES>>>();
    final_kernel<<<1, 1024>>>(out, n);
}